// round 13
// baseline (speedup 1.0000x reference)
#include <cuda_runtime.h>
#include <math.h>

#define NT 256
#define G 16
#define MAXSTEPS 4096
#define SMEM_FLOATS 41212
#define SMEM_BYTES (SMEM_FLOATS * 4)

// ---------------- persistent device state ----------------
__device__ float g_T[MAXSTEPS * 1024];   // per-step time-side gate contribution + folded biases
__device__ float g_UT[MAXSTEPS * 128];   // per-step tanh(LN(time enc layer1))
__device__ float g_M1[1024 * 128];       // w_ih[:, :128] @ se_w2
__device__ float g_M2t[128 * 1024];      // transpose of w_ih[:, 128:] @ te_w2
__device__ float g_Kc[1024];             // folded constant bias
__device__ float g_h0[256];              // initial hidden state (setup -> seq)
__device__ float g_curr[4];
__device__ float g_h2[2][256];           // parity-buffered h broadcast
__device__ float g_P[2][G * 256];        // parity-buffered head-1 partials
__device__ unsigned g_flag[G];           // per-CTA publish flags (monotonic per launch)
__device__ float g_LN[20];               // analytic state-encoder LN constants

__device__ __forceinline__ float sigm(float x) { return 1.0f / (1.0f + __expf(-x)); }

__device__ __forceinline__ void st_release(unsigned* p, unsigned v) {
    asm volatile("st.release.gpu.global.u32 [%0], %1;" :: "l"(p), "r"(v) : "memory");
}
__device__ __forceinline__ unsigned ld_acquire(const unsigned* p) {
    unsigned v;
    asm volatile("ld.acquire.gpu.global.u32 %0, [%1];" : "=r"(v) : "l"(p) : "memory");
    return v;
}

// sum over 128 active threads (tid<128 pass value, others 0); all 256 call.
__device__ __forceinline__ float blocksum128(float v, float* red) {
    int lane = threadIdx.x & 31, w = threadIdx.x >> 5;
#pragma unroll
    for (int o = 16; o > 0; o >>= 1) v += __shfl_down_sync(0xffffffffu, v, o);
    if (lane == 0) red[w] = v;
    __syncthreads();
    float s = red[0] + red[1] + red[2] + red[3];
    __syncthreads();
    return s;
}

// ---------------- precompute M1, M2t, Kc ----------------
__global__ void k_M(const float* __restrict__ w_ih, const float* __restrict__ se_w2,
                    const float* __restrict__ te_w2, const float* __restrict__ se_b2,
                    const float* __restrict__ te_b2, const float* __restrict__ b_ih,
                    const float* __restrict__ b_hh) {
    int r = blockIdx.x, j = threadIdx.x;  // 1024 x 128
    const float* wr = w_ih + r * 256;
    float s1 = 0.f, s2 = 0.f;
    for (int i = 0; i < 128; i++) s1 += wr[i] * se_w2[i * 128 + j];
    for (int i = 0; i < 128; i++) s2 += wr[128 + i] * te_w2[i * 128 + j];
    g_M1[r * 128 + j] = s1;
    g_M2t[j * 1024 + r] = s2;
    if (j == 0) {
        float kc = b_ih[r] + b_hh[r];
        for (int i = 0; i < 128; i++) kc += wr[i] * se_b2[i] + wr[128 + i] * te_b2[i];
        g_Kc[r] = kc;
    }
}

// ---------------- setup: flags, curr0, out row0, h0, LN constants ------------
__global__ void k_setup(const float* __restrict__ psi_re, const float* __restrict__ psi_im,
                        const float* __restrict__ t_start,
                        const float* __restrict__ se_w1, const float* __restrict__ se_b1,
                        const float* __restrict__ se_lng, const float* __restrict__ se_lnb,
                        const float* __restrict__ se_w2, const float* __restrict__ se_b2,
                        const float* __restrict__ te_w1, const float* __restrict__ te_b1,
                        const float* __restrict__ te_lng, const float* __restrict__ te_lnb,
                        const float* __restrict__ te_w2, const float* __restrict__ te_b2,
                        const float* __restrict__ hi_w, const float* __restrict__ hi_b,
                        float* __restrict__ out) {
    __shared__ float curr[4], u[128], comb[256], red[8];
    int tid = threadIdx.x;
    if (tid < G) g_flag[tid] = 0u;
    if (tid < 4) {
        float v = (tid < 2) ? psi_re[tid] : psi_im[tid - 2];
        curr[tid] = v; g_curr[tid] = v; out[tid] = v;
    }
    __syncthreads();

    // analytic-LN constants for the state encoder
    {
        float b = 0.f, w0 = 0.f, w1 = 0.f, w2 = 0.f, w3 = 0.f;
        if (tid < 128) {
            b = se_b1[tid];
            const float* w = se_w1 + tid * 4;
            w0 = w[0]; w1 = w[1]; w2 = w[2]; w3 = w[3];
        }
        const float inv = 0.0078125f;
        float vals[20] = { b, w0, w1, w2, w3,
                           b * b, 2.f * b * w0, 2.f * b * w1, 2.f * b * w2, 2.f * b * w3,
                           w0 * w0, w1 * w1, w2 * w2, w3 * w3,
                           2.f * w0 * w1, 2.f * w0 * w2, 2.f * w0 * w3,
                           2.f * w1 * w2, 2.f * w1 * w3, 2.f * w2 * w3 };
        for (int k = 0; k < 20; k++) {
            float s = blocksum128(vals[k], red);
            if (tid == 0) g_LN[k] = s * inv;
        }
    }

    float z = 0.f;
    if (tid < 128) {
        const float* w = se_w1 + tid * 4;
        z = se_b1[tid] + w[0] * curr[0] + w[1] * curr[1] + w[2] * curr[2] + w[3] * curr[3];
    }
    float m = blocksum128(tid < 128 ? z : 0.f, red) * 0.0078125f;
    float d = (tid < 128) ? z - m : 0.f;
    float var = blocksum128(d * d, red) * 0.0078125f;
    if (tid < 128) u[tid] = tanhf((z - m) * rsqrtf(var + 1e-5f) * se_lng[tid] + se_lnb[tid]);
    __syncthreads();
    if (tid < 128) {
        float s = se_b2[tid];
        for (int j = 0; j < 128; j++) s += se_w2[tid * 128 + j] * u[j];
        comb[tid] = s;
    }
    __syncthreads();
    float t0 = t_start[0];
    z = 0.f;
    if (tid < 128) z = te_b1[tid] + te_w1[tid] * t0;
    m = blocksum128(tid < 128 ? z : 0.f, red) * 0.0078125f;
    d = (tid < 128) ? z - m : 0.f;
    var = blocksum128(d * d, red) * 0.0078125f;
    if (tid < 128) u[tid] = tanhf((z - m) * rsqrtf(var + 1e-5f) * te_lng[tid] + te_lnb[tid]);
    __syncthreads();
    if (tid < 128) {
        float s = te_b2[tid];
        for (int j = 0; j < 128; j++) s += te_w2[tid * 128 + j] * u[j];
        comb[128 + tid] = s;
    }
    __syncthreads();
    {
        float s = hi_b[tid];
        for (int j = 0; j < 256; j++) s += hi_w[tid * 256 + j] * comb[j];
        g_h0[tid] = s;
    }
}

// ---------------- per-step time-encoder tanh(LN(.)) — exact two-pass ----------
__global__ void k_UT(const float* __restrict__ t_start, int steps,
                     const float* __restrict__ te_w1, const float* __restrict__ te_b1,
                     const float* __restrict__ te_lng, const float* __restrict__ te_lnb) {
    __shared__ float red[4];
    int tid = threadIdx.x;
    float t0 = t_start[0];
    float fS = (float)steps;
    float w1 = te_w1[tid], b1 = te_b1[tid], gg = te_lng[tid], bb = te_lnb[tid];
    for (int i = blockIdx.x; i < steps; i += gridDim.x) {
        float t = t0 - (float)(i + 1) / fS;
        float z = b1 + w1 * t;
        float m = blocksum128(z, red) * 0.0078125f;
        float d = z - m;
        float var = blocksum128(d * d, red) * 0.0078125f;
        g_UT[i * 128 + tid] = tanhf(d * rsqrtf(var + 1e-5f) * gg + bb);
        __syncthreads();
    }
}

// ---------------- T = UT @ M2^T + Kc ----------------
__global__ void k_TT(int steps) {
    __shared__ float UTs[16 * 128];
    int tid = threadIdx.x;
    int s0 = blockIdx.x * 16;
    int r = blockIdx.y * 256 + tid;
    for (int idx = tid; idx < 16 * 128; idx += 256) {
        int s = idx >> 7, j = idx & 127;
        UTs[idx] = (s0 + s < steps) ? g_UT[(s0 + s) * 128 + j] : 0.f;
    }
    __syncthreads();
    float acc[16];
#pragma unroll
    for (int s = 0; s < 16; s++) acc[s] = 0.f;
    for (int j = 0; j < 128; j++) {
        float mm = g_M2t[j * 1024 + r];
#pragma unroll
        for (int s = 0; s < 16; s++) acc[s] += mm * UTs[s * 128 + j];
    }
    float kc = g_Kc[r];
#pragma unroll
    for (int s = 0; s < 16; s++)
        if (s0 + s < steps) g_T[(s0 + s) * 1024 + r] = acc[s] + kc;
}

// ---------------- persistent sequential kernel ----------------
__global__ void __launch_bounds__(NT, 1) k_seq(
    const float* __restrict__ w_hh,
    const float* __restrict__ se_w1, const float* __restrict__ se_b1,
    const float* __restrict__ se_lng, const float* __restrict__ se_lnb,
    const float* __restrict__ sh_w1, const float* __restrict__ sh_b1,
    const float* __restrict__ sh_w2, const float* __restrict__ sh_b2,
    const float* __restrict__ sh_w3, const float* __restrict__ sh_b3,
    const float* __restrict__ dh_w1, const float* __restrict__ dh_b1,
    const float* __restrict__ dh_w2, const float* __restrict__ dh_b2,
    int steps, float* __restrict__ out) {
    extern __shared__ float sm[];
    float* Wg    = sm;            // [64][388]  gate rows (M1 | w_hh), f4-padded
    float* WhC   = sm + 24832;    // [256][17]  head-1 column slice
    float* W2    = sm + 29184;    // [64][132]  sh_w2, f4-padded
    float* w3s   = sm + 37632;    // [4][64]
    float* dw2s  = sm + 37888;    // [4][128]
    float* sew1  = sm + 38400;    // [128][4]
    float* seb1  = sm + 38912;    // [128]
    float* lng   = sm + 39040;    // [128]
    float* lnb   = sm + 39168;    // [128]
    float* hbias = sm + 39296;    // [256]  sh_b1 | dh_b1
    float* x     = sm + 39552;    // [384]  u(128) | h(256)
    float* vd    = sm + 39936;    // [256]  v1 | d1
    float* gpart = sm + 40192;    // [8][64]  parts 0-3: Whh*h, parts 4-7: M1*u
    float* vpart = sm + 40704;    // [4][64]
    float* sb2   = sm + 40960;    // [64]
    float* hs    = sm + 41024;    // [16]
    float* cs    = sm + 41040;    // [16]
    float* Ts    = sm + 41056;    // [64]
    float* shb3  = sm + 41120;    // [4]
    float* dhb2  = sm + 41124;    // [4]
    float* sd    = sm + 41128;    // [8]

    int tid = threadIdx.x, bid = blockIdx.x;

    // ---- prologue: stage weights ----
    for (int idx = tid; idx < 64 * 384; idx += NT) {
        int r = idx / 384, j = idx - r * 384;
        int R = (r >> 4) * 256 + bid * 16 + (r & 15);
        float v = (j < 128) ? g_M1[R * 128 + j] : w_hh[R * 256 + (j - 128)];
        Wg[r * 388 + j] = v;
    }
    for (int idx = tid; idx < 256 * 16; idx += NT) {
        int r = idx >> 4, l = idx & 15;
        int col = bid * 16 + l;
        WhC[r * 17 + l] = (r < 128) ? sh_w1[r * 256 + col] : dh_w1[(r - 128) * 256 + col];
    }
    for (int idx = tid; idx < 64 * 128; idx += NT) {
        int rr = idx >> 7, j = idx & 127;
        W2[rr * 132 + j] = sh_w2[idx];
    }
    w3s[tid] = sh_w3[tid];
    for (int idx = tid; idx < 512; idx += NT) { dw2s[idx] = dh_w2[idx]; sew1[idx] = se_w1[idx]; }
    if (tid < 128) { seb1[tid] = se_b1[tid]; lng[tid] = se_lng[tid]; lnb[tid] = se_lnb[tid]; }
    hbias[tid] = (tid < 128) ? sh_b1[tid] : dh_b1[tid - 128];
    if (tid < 64) sb2[tid] = sh_b2[tid];
    if (tid < 16) cs[tid] = 0.f;
    if (tid < 4) { shb3[tid] = sh_b3[tid]; dhb2[tid] = dh_b2[tid]; }
    x[128 + tid] = g_h0[tid];
    float cr0 = g_curr[0], cr1 = g_curr[1], cr2 = g_curr[2], cr3 = g_curr[3];
    float LN[20];
#pragma unroll
    for (int k = 0; k < 20; k++) LN[k] = g_LN[k];
    __syncthreads();

    const float* Trow = g_T + (tid >> 4) * 256 + bid * 16 + (tid & 15);
    float fS = (float)steps;

    // ================= step-0 pre-barrier compute =================
    if (tid < 64) Ts[tid] = Trow[0];
    {
        // Whh @ h0 partials
        int q = tid >> 6, row = tid & 63;
        const float4* wa = (const float4*)(Wg + row * 388 + 128 + q * 64);
        const float4* xp = (const float4*)(x + 128 + q * 64);
        float a = 0.f;
#pragma unroll
        for (int k = 0; k < 16; k++) {
            float4 w4 = wa[k], x4 = xp[k];
            a += w4.x * x4.x + w4.y * x4.y + w4.z * x4.z + w4.w * x4.w;
        }
        gpart[q * 64 + row] = a;
        // u via analytic LN
        float mB = LN[0] + LN[1] * cr0 + LN[2] * cr1 + LN[3] * cr2 + LN[4] * cr3;
        float e2 = LN[5] + LN[6] * cr0 + LN[7] * cr1 + LN[8] * cr2 + LN[9] * cr3
                 + LN[10] * cr0 * cr0 + LN[11] * cr1 * cr1 + LN[12] * cr2 * cr2 + LN[13] * cr3 * cr3
                 + LN[14] * cr0 * cr1 + LN[15] * cr0 * cr2 + LN[16] * cr0 * cr3
                 + LN[17] * cr1 * cr2 + LN[18] * cr1 * cr3 + LN[19] * cr2 * cr3;
        float rstd = rsqrtf(e2 - mB * mB + 1e-5f);
        if (tid < 128) {
            const float* w = sew1 + tid * 4;
            float z = seb1[tid] + w[0] * cr0 + w[1] * cr1 + w[2] * cr2 + w[3] * cr3;
            x[tid] = tanhf((z - mB) * rstd * lng[tid] + lnb[tid]);
        }
    }
    __syncthreads();
    {
        // M1 @ u partials
        int q = tid >> 6, row = tid & 63;
        const float4* wb = (const float4*)(Wg + row * 388 + q * 32);
        const float4* xu = (const float4*)(x + q * 32);
        float b = 0.f;
#pragma unroll
        for (int k = 0; k < 8; k++) {
            float4 w4 = wb[k], x4 = xu[k];
            b += w4.x * x4.x + w4.y * x4.y + w4.z * x4.z + w4.w * x4.w;
        }
        gpart[(4 + q) * 64 + row] = b;
    }
    __syncthreads();
    // LSTM: 64 threads, in-warp shfl combine
    if (tid < 64) {
        int wp = tid >> 5, lane = tid & 31;
        int gate = lane >> 3, ui = lane & 7;
        int unit = wp * 8 + ui;
        int gidx = gate * 16 + unit;
        float s = Ts[gidx];
#pragma unroll
        for (int q = 0; q < 8; q++) s += gpart[q * 64 + gidx];
        float act = (gate == 2) ? tanhf(s) : sigm(s);
        float af = __shfl_sync(0xffffffffu, act, 8 + ui);
        float ag = __shfl_sync(0xffffffffu, act, 16 + ui);
        float ao = __shfl_sync(0xffffffffu, act, 24 + ui);
        if (gate == 0) {
            float c = af * cs[unit] + act * ag;
            cs[unit] = c;
            float hn = ao * tanhf(c);
            hs[unit] = hn;
            __stcg(&g_h2[0][bid * 16 + unit], hn);
        }
    }
    __syncthreads();
    {
        const float* w = WhC + tid * 17;
        float a = 0.f;
#pragma unroll
        for (int l = 0; l < 16; l++) a += w[l] * hs[l];
        __stcg(&g_P[0][bid * 256 + tid], a);
    }
    __syncthreads();
    if (tid == 0) st_release(&g_flag[bid], 1u);

    // ================= main loop =================
    for (int i = 0; i < steps; ++i) {
        int p = i & 1, pn = p ^ 1;
        bool notlast = (i + 1 < steps);

        // fused barrier + h gather: spin thread t polls producer t's flag, then
        // immediately bulk-loads THAT producer's h slice (per-producer causality).
        if (tid < G) {
            unsigned tgt = (unsigned)(i + 1);
            while (ld_acquire(&g_flag[tid]) < tgt) { }
            const float4* hp = (const float4*)&g_h2[p][tid * 16];
            float4 h0 = __ldcg(hp), h1 = __ldcg(hp + 1), h2 = __ldcg(hp + 2), h3 = __ldcg(hp + 3);
            float4* xp4 = (float4*)&x[128 + tid * 16];
            xp4[0] = h0; xp4[1] = h1; xp4[2] = h2; xp4[3] = h3;
        }
        __syncthreads();  // S1 (merged): all flags seen, h staged

        // P loads (hidden under the Whh GEMV) + T prefetch for step i+1
        float pv[G];
#pragma unroll
        for (int b = 0; b < G; b++) pv[b] = __ldcg(&g_P[p][b * 256 + tid]);
        if (notlast && tid < 64) Ts[tid] = Trow[(i + 1) * 1024];

        // Whh @ h partials for NEXT gates — hides P-load latency
        if (notlast) {
            int q = tid >> 6, row = tid & 63;
            const float4* wa = (const float4*)(Wg + row * 388 + 128 + q * 64);
            const float4* xp = (const float4*)(x + 128 + q * 64);
            float a = 0.f;
#pragma unroll
            for (int k = 0; k < 16; k++) {
                float4 w4 = wa[k], x4 = xp[k];
                a += w4.x * x4.x + w4.y * x4.y + w4.z * x4.z + w4.w * x4.w;
            }
            gpart[q * 64 + row] = a;
        }
        // consume P partials
        {
            float s = hbias[tid];
#pragma unroll
            for (int b = 0; b < G; b++) s += pv[b];
            vd[tid] = tanhf(s);
        }
        __syncthreads();  // S3

        // v2 partials: 4 parts x 64 rows x 32 cols
        {
            int r = tid & 63, q = tid >> 6;
            const float4* w = (const float4*)(W2 + r * 132 + q * 32);
            const float4* xx = (const float4*)(vd + q * 32);
            float a = 0.f;
#pragma unroll
            for (int k = 0; k < 8; k++) {
                float4 w4 = w[k], x4 = xx[k];
                a += w4.x * x4.x + w4.y * x4.y + w4.z * x4.z + w4.w * x4.w;
            }
            vpart[q * 64 + r] = a;
        }
        __syncthreads();  // S4

        // heads
        {
            int w = tid >> 5, lane = tid & 31;
            float a;
            if (w < 4) {
                float vA = tanhf(sb2[lane] + vpart[lane] + vpart[64 + lane]
                                 + vpart[128 + lane] + vpart[192 + lane]);
                float vB = tanhf(sb2[32 + lane] + vpart[32 + lane] + vpart[96 + lane]
                                 + vpart[160 + lane] + vpart[224 + lane]);
                a = w3s[w * 64 + lane] * vA + w3s[w * 64 + 32 + lane] * vB;
            } else {
                int r = w - 4;
                const float* dw = dw2s + r * 128;
                const float* dx = vd + 128;
                a = dw[lane] * dx[lane] + dw[32 + lane] * dx[32 + lane]
                  + dw[64 + lane] * dx[64 + lane] + dw[96 + lane] * dx[96 + lane];
            }
#pragma unroll
            for (int o = 16; o > 0; o >>= 1) a += __shfl_down_sync(0xffffffffu, a, o);
            if (lane == 0) sd[w] = a + ((w < 4) ? shb3[w] : dhb2[w - 4]);
        }
        __syncthreads();  // S5

        // curr update + renorm (every thread, identical FP) + out
        {
            float ss = 0.02f * (1.0f - (float)i / fS);
            float n0 = cr0 + ss * (sd[4] + 0.5f * sd[0]);
            float n1 = cr1 + ss * (sd[5] + 0.5f * sd[1]);
            float n2 = cr2 + ss * (sd[6] + 0.5f * sd[2]);
            float n3 = cr3 + ss * (sd[7] + 0.5f * sd[3]);
            float s2 = n0 * n0 + n1 * n1 + n2 * n2 + n3 * n3;
            float inv = 1.0f / (sqrtf(s2) + 1e-8f);
            cr0 = n0 * inv; cr1 = n1 * inv; cr2 = n2 * inv; cr3 = n3 * inv;
            if (bid == 0 && tid == 0) {
                float* o = out + (i + 1) * 4;
                o[0] = cr0; o[1] = cr1; o[2] = cr2; o[3] = cr3;
            }
        }
        if (!notlast) break;

        // u via analytic LN (no reduction, no extra sync)
        {
            float mB = LN[0] + LN[1] * cr0 + LN[2] * cr1 + LN[3] * cr2 + LN[4] * cr3;
            float e2 = LN[5] + LN[6] * cr0 + LN[7] * cr1 + LN[8] * cr2 + LN[9] * cr3
                     + LN[10] * cr0 * cr0 + LN[11] * cr1 * cr1 + LN[12] * cr2 * cr2 + LN[13] * cr3 * cr3
                     + LN[14] * cr0 * cr1 + LN[15] * cr0 * cr2 + LN[16] * cr0 * cr3
                     + LN[17] * cr1 * cr2 + LN[18] * cr1 * cr3 + LN[19] * cr2 * cr3;
            float rstd = rsqrtf(e2 - mB * mB + 1e-5f);
            if (tid < 128) {
                const float* w = sew1 + tid * 4;
                float z = seb1[tid] + w[0] * cr0 + w[1] * cr1 + w[2] * cr2 + w[3] * cr3;
                x[tid] = tanhf((z - mB) * rstd * lng[tid] + lnb[tid]);
            }
        }
        __syncthreads();  // S6

        // M1 @ u partials
        {
            int q = tid >> 6, row = tid & 63;
            const float4* wb = (const float4*)(Wg + row * 388 + q * 32);
            const float4* xu = (const float4*)(x + q * 32);
            float b = 0.f;
#pragma unroll
            for (int k = 0; k < 8; k++) {
                float4 w4 = wb[k], x4 = xu[k];
                b += w4.x * x4.x + w4.y * x4.y + w4.z * x4.z + w4.w * x4.w;
            }
            gpart[(4 + q) * 64 + row] = b;
        }
        __syncthreads();  // S7

        // LSTM: 64 threads, in-warp shfl combine
        if (tid < 64) {
            int wp = tid >> 5, lane = tid & 31;
            int gate = lane >> 3, ui = lane & 7;
            int unit = wp * 8 + ui;
            int gidx = gate * 16 + unit;
            float s = Ts[gidx];
#pragma unroll
            for (int q = 0; q < 8; q++) s += gpart[q * 64 + gidx];
            float act = (gate == 2) ? tanhf(s) : sigm(s);
            float af = __shfl_sync(0xffffffffu, act, 8 + ui);
            float ag = __shfl_sync(0xffffffffu, act, 16 + ui);
            float ao = __shfl_sync(0xffffffffu, act, 24 + ui);
            if (gate == 0) {
                float c = af * cs[unit] + act * ag;
                cs[unit] = c;
                float hn = ao * tanhf(c);
                hs[unit] = hn;
                __stcg(&g_h2[pn][bid * 16 + unit], hn);
            }
        }
        __syncthreads();  // S8

        // head-1 partial from own h slice, publish
        {
            const float* w = WhC + tid * 17;
            float a = 0.f;
#pragma unroll
            for (int l = 0; l < 16; l++) a += w[l] * hs[l];
            __stcg(&g_P[pn][bid * 256 + tid], a);
        }
        __syncthreads();  // S9
        if (tid == 0) st_release(&g_flag[bid], (unsigned)(i + 2));
    }
}

extern "C" void kernel_launch(void* const* d_in, const int* in_sizes, int n_in,
                              void* d_out, int out_size) {
    int off = (n_in >= 32) ? 4 : 3;
    const float* psi_re  = (const float*)d_in[0];
    const float* psi_im  = (const float*)d_in[1];
    const float* t_start = (const float*)d_in[2];
    const float* se_w1 = (const float*)d_in[off + 0];
    const float* se_b1 = (const float*)d_in[off + 1];
    const float* se_lng = (const float*)d_in[off + 2];
    const float* se_lnb = (const float*)d_in[off + 3];
    const float* se_w2 = (const float*)d_in[off + 4];
    const float* se_b2 = (const float*)d_in[off + 5];
    const float* te_w1 = (const float*)d_in[off + 6];
    const float* te_b1 = (const float*)d_in[off + 7];
    const float* te_lng = (const float*)d_in[off + 8];
    const float* te_lnb = (const float*)d_in[off + 9];
    const float* te_w2 = (const float*)d_in[off + 10];
    const float* te_b2 = (const float*)d_in[off + 11];
    const float* w_ih = (const float*)d_in[off + 12];
    const float* w_hh = (const float*)d_in[off + 13];
    const float* b_ih = (const float*)d_in[off + 14];
    const float* b_hh = (const float*)d_in[off + 15];
    const float* hi_w = (const float*)d_in[off + 16];
    const float* hi_b = (const float*)d_in[off + 17];
    const float* sh_w1 = (const float*)d_in[off + 18];
    const float* sh_b1 = (const float*)d_in[off + 19];
    const float* sh_w2 = (const float*)d_in[off + 20];
    const float* sh_b2 = (const float*)d_in[off + 21];
    const float* sh_w3 = (const float*)d_in[off + 22];
    const float* sh_b3 = (const float*)d_in[off + 23];
    const float* dh_w1 = (const float*)d_in[off + 24];
    const float* dh_b1 = (const float*)d_in[off + 25];
    const float* dh_w2 = (const float*)d_in[off + 26];
    const float* dh_b2 = (const float*)d_in[off + 27];
    float* out = (float*)d_out;

    int steps = out_size / 4 - 1;
    if (steps > MAXSTEPS) steps = MAXSTEPS;
    if (steps < 1) steps = 1;

    cudaFuncSetAttribute(k_seq, cudaFuncAttributeMaxDynamicSharedMemorySize, SMEM_BYTES);

    k_M<<<1024, 128>>>(w_ih, se_w2, te_w2, se_b2, te_b2, b_ih, b_hh);
    k_setup<<<1, 256>>>(psi_re, psi_im, t_start,
                        se_w1, se_b1, se_lng, se_lnb, se_w2, se_b2,
                        te_w1, te_b1, te_lng, te_lnb, te_w2, te_b2,
                        hi_w, hi_b, out);
    k_UT<<<256, 128>>>(t_start, steps, te_w1, te_b1, te_lng, te_lnb);
    k_TT<<<dim3((steps + 15) / 16, 4), 256>>>(steps);
    k_seq<<<G, NT, SMEM_BYTES>>>(w_hh,
                                 se_w1, se_b1, se_lng, se_lnb,
                                 sh_w1, sh_b1, sh_w2, sh_b2, sh_w3, sh_b3,
                                 dh_w1, dh_b1, dh_w2, dh_b2,
                                 steps, out);
}

// round 14
// speedup vs baseline: 1.1100x; 1.1100x over previous
#include <cuda_runtime.h>
#include <math.h>

#define NT 256
#define G 16
#define MAXSTEPS 4096
#define SMEM_FLOATS 41212
#define SMEM_BYTES (SMEM_FLOATS * 4)

// ---------------- persistent device state ----------------
__device__ float g_T[MAXSTEPS * 1024];   // per-step time-side gate contribution + folded biases
__device__ float g_UT[MAXSTEPS * 128];   // per-step tanh(LN(time enc layer1))
__device__ float g_M1[1024 * 128];       // w_ih[:, :128] @ se_w2
__device__ float g_M2t[128 * 1024];      // transpose of w_ih[:, 128:] @ te_w2
__device__ float g_Kc[1024];             // folded constant bias
__device__ float g_h0[256];              // initial hidden state (setup -> seq)
__device__ float g_curr[4];
__device__ float g_h2[2][256];           // parity-buffered h broadcast
__device__ float g_P[2][G * 256];        // parity-buffered head-1 partials
__device__ unsigned g_flag[G];           // per-CTA publish flags (monotonic per launch)
__device__ float g_LN[20];               // analytic state-encoder LN constants

__device__ __forceinline__ float sigm(float x) {
    return __fdividef(1.0f, 1.0f + __expf(-x));
}

__device__ __forceinline__ void st_release(unsigned* p, unsigned v) {
    asm volatile("st.release.gpu.global.u32 [%0], %1;" :: "l"(p), "r"(v) : "memory");
}
__device__ __forceinline__ unsigned ld_acquire(const unsigned* p) {
    unsigned v;
    asm volatile("ld.acquire.gpu.global.u32 %0, [%1];" : "=r"(v) : "l"(p) : "memory");
    return v;
}

// sum over 128 active threads (tid<128 pass value, others 0); all 256 call.
__device__ __forceinline__ float blocksum128(float v, float* red) {
    int lane = threadIdx.x & 31, w = threadIdx.x >> 5;
#pragma unroll
    for (int o = 16; o > 0; o >>= 1) v += __shfl_down_sync(0xffffffffu, v, o);
    if (lane == 0) red[w] = v;
    __syncthreads();
    float s = red[0] + red[1] + red[2] + red[3];
    __syncthreads();
    return s;
}

// ---------------- precompute M1, M2t, Kc ----------------
__global__ void k_M(const float* __restrict__ w_ih, const float* __restrict__ se_w2,
                    const float* __restrict__ te_w2, const float* __restrict__ se_b2,
                    const float* __restrict__ te_b2, const float* __restrict__ b_ih,
                    const float* __restrict__ b_hh) {
    int r = blockIdx.x, j = threadIdx.x;  // 1024 x 128
    const float* wr = w_ih + r * 256;
    float s1 = 0.f, s2 = 0.f;
    for (int i = 0; i < 128; i++) s1 += wr[i] * se_w2[i * 128 + j];
    for (int i = 0; i < 128; i++) s2 += wr[128 + i] * te_w2[i * 128 + j];
    g_M1[r * 128 + j] = s1;
    g_M2t[j * 1024 + r] = s2;
    if (j == 0) {
        float kc = b_ih[r] + b_hh[r];
        for (int i = 0; i < 128; i++) kc += wr[i] * se_b2[i] + wr[128 + i] * te_b2[i];
        g_Kc[r] = kc;
    }
}

// ---------------- setup: flags, curr0, out row0, h0, LN constants ------------
__global__ void k_setup(const float* __restrict__ psi_re, const float* __restrict__ psi_im,
                        const float* __restrict__ t_start,
                        const float* __restrict__ se_w1, const float* __restrict__ se_b1,
                        const float* __restrict__ se_lng, const float* __restrict__ se_lnb,
                        const float* __restrict__ se_w2, const float* __restrict__ se_b2,
                        const float* __restrict__ te_w1, const float* __restrict__ te_b1,
                        const float* __restrict__ te_lng, const float* __restrict__ te_lnb,
                        const float* __restrict__ te_w2, const float* __restrict__ te_b2,
                        const float* __restrict__ hi_w, const float* __restrict__ hi_b,
                        float* __restrict__ out) {
    __shared__ float curr[4], u[128], comb[256], red[8];
    int tid = threadIdx.x;
    if (tid < G) g_flag[tid] = 0u;
    if (tid < 4) {
        float v = (tid < 2) ? psi_re[tid] : psi_im[tid - 2];
        curr[tid] = v; g_curr[tid] = v; out[tid] = v;
    }
    __syncthreads();

    // analytic-LN constants for the state encoder
    {
        float b = 0.f, w0 = 0.f, w1 = 0.f, w2 = 0.f, w3 = 0.f;
        if (tid < 128) {
            b = se_b1[tid];
            const float* w = se_w1 + tid * 4;
            w0 = w[0]; w1 = w[1]; w2 = w[2]; w3 = w[3];
        }
        const float inv = 0.0078125f;
        float vals[20] = { b, w0, w1, w2, w3,
                           b * b, 2.f * b * w0, 2.f * b * w1, 2.f * b * w2, 2.f * b * w3,
                           w0 * w0, w1 * w1, w2 * w2, w3 * w3,
                           2.f * w0 * w1, 2.f * w0 * w2, 2.f * w0 * w3,
                           2.f * w1 * w2, 2.f * w1 * w3, 2.f * w2 * w3 };
        for (int k = 0; k < 20; k++) {
            float s = blocksum128(vals[k], red);
            if (tid == 0) g_LN[k] = s * inv;
        }
    }

    float z = 0.f;
    if (tid < 128) {
        const float* w = se_w1 + tid * 4;
        z = se_b1[tid] + w[0] * curr[0] + w[1] * curr[1] + w[2] * curr[2] + w[3] * curr[3];
    }
    float m = blocksum128(tid < 128 ? z : 0.f, red) * 0.0078125f;
    float d = (tid < 128) ? z - m : 0.f;
    float var = blocksum128(d * d, red) * 0.0078125f;
    if (tid < 128) u[tid] = tanhf((z - m) * rsqrtf(var + 1e-5f) * se_lng[tid] + se_lnb[tid]);
    __syncthreads();
    if (tid < 128) {
        float s = se_b2[tid];
        for (int j = 0; j < 128; j++) s += se_w2[tid * 128 + j] * u[j];
        comb[tid] = s;
    }
    __syncthreads();
    float t0 = t_start[0];
    z = 0.f;
    if (tid < 128) z = te_b1[tid] + te_w1[tid] * t0;
    m = blocksum128(tid < 128 ? z : 0.f, red) * 0.0078125f;
    d = (tid < 128) ? z - m : 0.f;
    var = blocksum128(d * d, red) * 0.0078125f;
    if (tid < 128) u[tid] = tanhf((z - m) * rsqrtf(var + 1e-5f) * te_lng[tid] + te_lnb[tid]);
    __syncthreads();
    if (tid < 128) {
        float s = te_b2[tid];
        for (int j = 0; j < 128; j++) s += te_w2[tid * 128 + j] * u[j];
        comb[128 + tid] = s;
    }
    __syncthreads();
    {
        float s = hi_b[tid];
        for (int j = 0; j < 256; j++) s += hi_w[tid * 256 + j] * comb[j];
        g_h0[tid] = s;
    }
}

// ---------------- per-step time-encoder tanh(LN(.)) — exact two-pass ----------
__global__ void k_UT(const float* __restrict__ t_start, int steps,
                     const float* __restrict__ te_w1, const float* __restrict__ te_b1,
                     const float* __restrict__ te_lng, const float* __restrict__ te_lnb) {
    __shared__ float red[4];
    int tid = threadIdx.x;
    float t0 = t_start[0];
    float fS = (float)steps;
    float w1 = te_w1[tid], b1 = te_b1[tid], gg = te_lng[tid], bb = te_lnb[tid];
    for (int i = blockIdx.x; i < steps; i += gridDim.x) {
        float t = t0 - (float)(i + 1) / fS;
        float z = b1 + w1 * t;
        float m = blocksum128(z, red) * 0.0078125f;
        float d = z - m;
        float var = blocksum128(d * d, red) * 0.0078125f;
        g_UT[i * 128 + tid] = tanhf(d * rsqrtf(var + 1e-5f) * gg + bb);
        __syncthreads();
    }
}

// ---------------- T = UT @ M2^T + Kc ----------------
__global__ void k_TT(int steps) {
    __shared__ float UTs[16 * 128];
    int tid = threadIdx.x;
    int s0 = blockIdx.x * 16;
    int r = blockIdx.y * 256 + tid;
    for (int idx = tid; idx < 16 * 128; idx += 256) {
        int s = idx >> 7, j = idx & 127;
        UTs[idx] = (s0 + s < steps) ? g_UT[(s0 + s) * 128 + j] : 0.f;
    }
    __syncthreads();
    float acc[16];
#pragma unroll
    for (int s = 0; s < 16; s++) acc[s] = 0.f;
    for (int j = 0; j < 128; j++) {
        float mm = g_M2t[j * 1024 + r];
#pragma unroll
        for (int s = 0; s < 16; s++) acc[s] += mm * UTs[s * 128 + j];
    }
    float kc = g_Kc[r];
#pragma unroll
    for (int s = 0; s < 16; s++)
        if (s0 + s < steps) g_T[(s0 + s) * 1024 + r] = acc[s] + kc;
}

// ---------------- persistent sequential kernel ----------------
__global__ void __launch_bounds__(NT, 1) k_seq(
    const float* __restrict__ w_hh,
    const float* __restrict__ se_w1, const float* __restrict__ se_b1,
    const float* __restrict__ se_lng, const float* __restrict__ se_lnb,
    const float* __restrict__ sh_w1, const float* __restrict__ sh_b1,
    const float* __restrict__ sh_w2, const float* __restrict__ sh_b2,
    const float* __restrict__ sh_w3, const float* __restrict__ sh_b3,
    const float* __restrict__ dh_w1, const float* __restrict__ dh_b1,
    const float* __restrict__ dh_w2, const float* __restrict__ dh_b2,
    int steps, float* __restrict__ out) {
    extern __shared__ float sm[];
    float* Wg    = sm;            // [64][388]  gate rows (M1 | w_hh), f4-padded
    float* WhC   = sm + 24832;    // [256][17]  head-1 column slice
    float* W2    = sm + 29184;    // [64][132]  sh_w2, f4-padded
    float* w3s   = sm + 37632;    // [4][64]
    float* dw2s  = sm + 37888;    // [4][128]
    float* sew1  = sm + 38400;    // [128][4]
    float* seb1  = sm + 38912;    // [128]
    float* lng   = sm + 39040;    // [128]
    float* lnb   = sm + 39168;    // [128]
    float* hbias = sm + 39296;    // [256]  sh_b1 | dh_b1
    float* x     = sm + 39552;    // [384]  u(128) | h(256)
    float* vd    = sm + 39936;    // [256]  v1 | d1
    float* gpart = sm + 40192;    // [8][64]  parts 0-3: Whh*h, parts 4-7: M1*u
    float* vpart = sm + 40704;    // [4][64]
    float* sb2   = sm + 40960;    // [64]
    float* hs    = sm + 41024;    // [16]
    float* cs    = sm + 41040;    // [16]
    float* Ts    = sm + 41056;    // [64]
    float* shb3  = sm + 41120;    // [4]
    float* dhb2  = sm + 41124;    // [4]
    float* sd    = sm + 41128;    // [8]

    int tid = threadIdx.x, bid = blockIdx.x;

    // ---- prologue: stage weights ----
    for (int idx = tid; idx < 64 * 384; idx += NT) {
        int r = idx / 384, j = idx - r * 384;
        int R = (r >> 4) * 256 + bid * 16 + (r & 15);
        float v = (j < 128) ? g_M1[R * 128 + j] : w_hh[R * 256 + (j - 128)];
        Wg[r * 388 + j] = v;
    }
    for (int idx = tid; idx < 256 * 16; idx += NT) {
        int r = idx >> 4, l = idx & 15;
        int col = bid * 16 + l;
        WhC[r * 17 + l] = (r < 128) ? sh_w1[r * 256 + col] : dh_w1[(r - 128) * 256 + col];
    }
    for (int idx = tid; idx < 64 * 128; idx += NT) {
        int rr = idx >> 7, j = idx & 127;
        W2[rr * 132 + j] = sh_w2[idx];
    }
    w3s[tid] = sh_w3[tid];
    for (int idx = tid; idx < 512; idx += NT) { dw2s[idx] = dh_w2[idx]; sew1[idx] = se_w1[idx]; }
    if (tid < 128) { seb1[tid] = se_b1[tid]; lng[tid] = se_lng[tid]; lnb[tid] = se_lnb[tid]; }
    hbias[tid] = (tid < 128) ? sh_b1[tid] : dh_b1[tid - 128];
    if (tid < 64) sb2[tid] = sh_b2[tid];
    if (tid < 16) cs[tid] = 0.f;
    if (tid < 4) { shb3[tid] = sh_b3[tid]; dhb2[tid] = dh_b2[tid]; }
    x[128 + tid] = g_h0[tid];
    float cr0 = g_curr[0], cr1 = g_curr[1], cr2 = g_curr[2], cr3 = g_curr[3];
    float LN[20];
#pragma unroll
    for (int k = 0; k < 20; k++) LN[k] = g_LN[k];
    __syncthreads();

    const float* Trow = g_T + (tid >> 4) * 256 + bid * 16 + (tid & 15);
    float fS = (float)steps;

    // ================= step-0 pre-barrier compute =================
    if (tid < 64) Ts[tid] = Trow[0];
    {
        // Whh @ h0 partials
        int q = tid >> 6, row = tid & 63;
        const float4* wa = (const float4*)(Wg + row * 388 + 128 + q * 64);
        const float4* xp = (const float4*)(x + 128 + q * 64);
        float a = 0.f;
#pragma unroll
        for (int k = 0; k < 16; k++) {
            float4 w4 = wa[k], x4 = xp[k];
            a += w4.x * x4.x + w4.y * x4.y + w4.z * x4.z + w4.w * x4.w;
        }
        gpart[q * 64 + row] = a;
        // u via analytic LN
        float mB = LN[0] + LN[1] * cr0 + LN[2] * cr1 + LN[3] * cr2 + LN[4] * cr3;
        float e2 = LN[5] + LN[6] * cr0 + LN[7] * cr1 + LN[8] * cr2 + LN[9] * cr3
                 + LN[10] * cr0 * cr0 + LN[11] * cr1 * cr1 + LN[12] * cr2 * cr2 + LN[13] * cr3 * cr3
                 + LN[14] * cr0 * cr1 + LN[15] * cr0 * cr2 + LN[16] * cr0 * cr3
                 + LN[17] * cr1 * cr2 + LN[18] * cr1 * cr3 + LN[19] * cr2 * cr3;
        float rstd = rsqrtf(e2 - mB * mB + 1e-5f);
        if (tid < 128) {
            const float* w = sew1 + tid * 4;
            float z = seb1[tid] + w[0] * cr0 + w[1] * cr1 + w[2] * cr2 + w[3] * cr3;
            x[tid] = tanhf((z - mB) * rstd * lng[tid] + lnb[tid]);
        }
    }
    __syncthreads();
    {
        // M1 @ u partials
        int q = tid >> 6, row = tid & 63;
        const float4* wb = (const float4*)(Wg + row * 388 + q * 32);
        const float4* xu = (const float4*)(x + q * 32);
        float b = 0.f;
#pragma unroll
        for (int k = 0; k < 8; k++) {
            float4 w4 = wb[k], x4 = xu[k];
            b += w4.x * x4.x + w4.y * x4.y + w4.z * x4.z + w4.w * x4.w;
        }
        gpart[(4 + q) * 64 + row] = b;
    }
    __syncthreads();
    // LSTM: 64 threads, in-warp shfl combine
    if (tid < 64) {
        int wp = tid >> 5, lane = tid & 31;
        int gate = lane >> 3, ui = lane & 7;
        int unit = wp * 8 + ui;
        int gidx = gate * 16 + unit;
        float s = Ts[gidx];
#pragma unroll
        for (int q = 0; q < 8; q++) s += gpart[q * 64 + gidx];
        float act = (gate == 2) ? tanhf(s) : sigm(s);
        float af = __shfl_sync(0xffffffffu, act, 8 + ui);
        float ag = __shfl_sync(0xffffffffu, act, 16 + ui);
        float ao = __shfl_sync(0xffffffffu, act, 24 + ui);
        if (gate == 0) {
            float c = af * cs[unit] + act * ag;
            cs[unit] = c;
            float hn = ao * tanhf(c);
            hs[unit] = hn;
            __stcg(&g_h2[0][bid * 16 + unit], hn);
        }
    }
    __syncthreads();
    {
        const float* w = WhC + tid * 17;
        float a = 0.f;
#pragma unroll
        for (int l = 0; l < 16; l++) a += w[l] * hs[l];
        __stcg(&g_P[0][bid * 256 + tid], a);
    }
    __syncthreads();
    if (tid == 0) st_release(&g_flag[bid], 1u);

    // ================= main loop =================
    for (int i = 0; i < steps; ++i) {
        int p = i & 1, pn = p ^ 1;
        bool notlast = (i + 1 < steps);

        // barrier: wait all CTAs' publishes for step i
        if (tid < G) {
            unsigned tgt = (unsigned)(i + 1);
            while (ld_acquire(&g_flag[tid]) < tgt) { }
        }
        __syncthreads();  // S1

        // gather: issue h + P loads (MLP); prefetch T for step i+1
        float hv = __ldcg(&g_h2[p][tid]);
        float pv[G];
#pragma unroll
        for (int b = 0; b < G; b++) pv[b] = __ldcg(&g_P[p][b * 256 + tid]);
        if (notlast && tid < 64) Ts[tid] = Trow[(i + 1) * 1024];
        x[128 + tid] = hv;
        __syncthreads();  // S2

        // Whh @ h partials for NEXT gates — hides P-load latency
        if (notlast) {
            int q = tid >> 6, row = tid & 63;
            const float4* wa = (const float4*)(Wg + row * 388 + 128 + q * 64);
            const float4* xp = (const float4*)(x + 128 + q * 64);
            float a = 0.f;
#pragma unroll
            for (int k = 0; k < 16; k++) {
                float4 w4 = wa[k], x4 = xp[k];
                a += w4.x * x4.x + w4.y * x4.y + w4.z * x4.z + w4.w * x4.w;
            }
            gpart[q * 64 + row] = a;
        }
        // consume P partials (arrived during GEMV)
        {
            float s = hbias[tid];
#pragma unroll
            for (int b = 0; b < G; b++) s += pv[b];
            vd[tid] = tanhf(s);
        }
        __syncthreads();  // S3

        // v2 partials: 4 parts x 64 rows x 32 cols
        {
            int r = tid & 63, q = tid >> 6;
            const float4* w = (const float4*)(W2 + r * 132 + q * 32);
            const float4* xx = (const float4*)(vd + q * 32);
            float a = 0.f;
#pragma unroll
            for (int k = 0; k < 8; k++) {
                float4 w4 = w[k], x4 = xx[k];
                a += w4.x * x4.x + w4.y * x4.y + w4.z * x4.z + w4.w * x4.w;
            }
            vpart[q * 64 + r] = a;
        }
        __syncthreads();  // S4

        // heads
        {
            int w = tid >> 5, lane = tid & 31;
            float a;
            if (w < 4) {
                float vA = tanhf(sb2[lane] + vpart[lane] + vpart[64 + lane]
                                 + vpart[128 + lane] + vpart[192 + lane]);
                float vB = tanhf(sb2[32 + lane] + vpart[32 + lane] + vpart[96 + lane]
                                 + vpart[160 + lane] + vpart[224 + lane]);
                a = w3s[w * 64 + lane] * vA + w3s[w * 64 + 32 + lane] * vB;
            } else {
                int r = w - 4;
                const float* dw = dw2s + r * 128;
                const float* dx = vd + 128;
                a = dw[lane] * dx[lane] + dw[32 + lane] * dx[32 + lane]
                  + dw[64 + lane] * dx[64 + lane] + dw[96 + lane] * dx[96 + lane];
            }
#pragma unroll
            for (int o = 16; o > 0; o >>= 1) a += __shfl_down_sync(0xffffffffu, a, o);
            if (lane == 0) sd[w] = a + ((w < 4) ? shb3[w] : dhb2[w - 4]);
        }
        __syncthreads();  // S5

        // curr update + renorm (every thread, identical FP) + out
        {
            float ss = 0.02f * (1.0f - (float)i / fS);
            float n0 = cr0 + ss * (sd[4] + 0.5f * sd[0]);
            float n1 = cr1 + ss * (sd[5] + 0.5f * sd[1]);
            float n2 = cr2 + ss * (sd[6] + 0.5f * sd[2]);
            float n3 = cr3 + ss * (sd[7] + 0.5f * sd[3]);
            float s2 = n0 * n0 + n1 * n1 + n2 * n2 + n3 * n3;
            float inv = 1.0f / (sqrtf(s2) + 1e-8f);
            cr0 = n0 * inv; cr1 = n1 * inv; cr2 = n2 * inv; cr3 = n3 * inv;
            if (bid == 0 && tid == 0) {
                float* o = out + (i + 1) * 4;
                o[0] = cr0; o[1] = cr1; o[2] = cr2; o[3] = cr3;
            }
        }
        if (!notlast) break;

        // u via analytic LN (no reduction, no extra sync)
        {
            float mB = LN[0] + LN[1] * cr0 + LN[2] * cr1 + LN[3] * cr2 + LN[4] * cr3;
            float e2 = LN[5] + LN[6] * cr0 + LN[7] * cr1 + LN[8] * cr2 + LN[9] * cr3
                     + LN[10] * cr0 * cr0 + LN[11] * cr1 * cr1 + LN[12] * cr2 * cr2 + LN[13] * cr3 * cr3
                     + LN[14] * cr0 * cr1 + LN[15] * cr0 * cr2 + LN[16] * cr0 * cr3
                     + LN[17] * cr1 * cr2 + LN[18] * cr1 * cr3 + LN[19] * cr2 * cr3;
            float rstd = rsqrtf(e2 - mB * mB + 1e-5f);
            if (tid < 128) {
                const float* w = sew1 + tid * 4;
                float z = seb1[tid] + w[0] * cr0 + w[1] * cr1 + w[2] * cr2 + w[3] * cr3;
                x[tid] = tanhf((z - mB) * rstd * lng[tid] + lnb[tid]);
            }
        }
        __syncthreads();  // S6

        // M1 @ u partials
        {
            int q = tid >> 6, row = tid & 63;
            const float4* wb = (const float4*)(Wg + row * 388 + q * 32);
            const float4* xu = (const float4*)(x + q * 32);
            float b = 0.f;
#pragma unroll
            for (int k = 0; k < 8; k++) {
                float4 w4 = wb[k], x4 = xu[k];
                b += w4.x * x4.x + w4.y * x4.y + w4.z * x4.z + w4.w * x4.w;
            }
            gpart[(4 + q) * 64 + row] = b;
        }
        __syncthreads();  // S7

        // LSTM: 64 threads, in-warp shfl combine
        if (tid < 64) {
            int wp = tid >> 5, lane = tid & 31;
            int gate = lane >> 3, ui = lane & 7;
            int unit = wp * 8 + ui;
            int gidx = gate * 16 + unit;
            float s = Ts[gidx];
#pragma unroll
            for (int q = 0; q < 8; q++) s += gpart[q * 64 + gidx];
            float act = (gate == 2) ? tanhf(s) : sigm(s);
            float af = __shfl_sync(0xffffffffu, act, 8 + ui);
            float ag = __shfl_sync(0xffffffffu, act, 16 + ui);
            float ao = __shfl_sync(0xffffffffu, act, 24 + ui);
            if (gate == 0) {
                float c = af * cs[unit] + act * ag;
                cs[unit] = c;
                float hn = ao * tanhf(c);
                hs[unit] = hn;
                __stcg(&g_h2[pn][bid * 16 + unit], hn);
            }
        }
        __syncthreads();  // S8

        // head-1 partial from own h slice, publish
        {
            const float* w = WhC + tid * 17;
            float a = 0.f;
#pragma unroll
            for (int l = 0; l < 16; l++) a += w[l] * hs[l];
            __stcg(&g_P[pn][bid * 256 + tid], a);
        }
        __syncthreads();  // S9
        if (tid == 0) st_release(&g_flag[bid], (unsigned)(i + 2));
    }
}

extern "C" void kernel_launch(void* const* d_in, const int* in_sizes, int n_in,
                              void* d_out, int out_size) {
    int off = (n_in >= 32) ? 4 : 3;
    const float* psi_re  = (const float*)d_in[0];
    const float* psi_im  = (const float*)d_in[1];
    const float* t_start = (const float*)d_in[2];
    const float* se_w1 = (const float*)d_in[off + 0];
    const float* se_b1 = (const float*)d_in[off + 1];
    const float* se_lng = (const float*)d_in[off + 2];
    const float* se_lnb = (const float*)d_in[off + 3];
    const float* se_w2 = (const float*)d_in[off + 4];
    const float* se_b2 = (const float*)d_in[off + 5];
    const float* te_w1 = (const float*)d_in[off + 6];
    const float* te_b1 = (const float*)d_in[off + 7];
    const float* te_lng = (const float*)d_in[off + 8];
    const float* te_lnb = (const float*)d_in[off + 9];
    const float* te_w2 = (const float*)d_in[off + 10];
    const float* te_b2 = (const float*)d_in[off + 11];
    const float* w_ih = (const float*)d_in[off + 12];
    const float* w_hh = (const float*)d_in[off + 13];
    const float* b_ih = (const float*)d_in[off + 14];
    const float* b_hh = (const float*)d_in[off + 15];
    const float* hi_w = (const float*)d_in[off + 16];
    const float* hi_b = (const float*)d_in[off + 17];
    const float* sh_w1 = (const float*)d_in[off + 18];
    const float* sh_b1 = (const float*)d_in[off + 19];
    const float* sh_w2 = (const float*)d_in[off + 20];
    const float* sh_b2 = (const float*)d_in[off + 21];
    const float* sh_w3 = (const float*)d_in[off + 22];
    const float* sh_b3 = (const float*)d_in[off + 23];
    const float* dh_w1 = (const float*)d_in[off + 24];
    const float* dh_b1 = (const float*)d_in[off + 25];
    const float* dh_w2 = (const float*)d_in[off + 26];
    const float* dh_b2 = (const float*)d_in[off + 27];
    float* out = (float*)d_out;

    int steps = out_size / 4 - 1;
    if (steps > MAXSTEPS) steps = MAXSTEPS;
    if (steps < 1) steps = 1;

    cudaFuncSetAttribute(k_seq, cudaFuncAttributeMaxDynamicSharedMemorySize, SMEM_BYTES);

    k_M<<<1024, 128>>>(w_ih, se_w2, te_w2, se_b2, te_b2, b_ih, b_hh);
    k_setup<<<1, 256>>>(psi_re, psi_im, t_start,
                        se_w1, se_b1, se_lng, se_lnb, se_w2, se_b2,
                        te_w1, te_b1, te_lng, te_lnb, te_w2, te_b2,
                        hi_w, hi_b, out);
    k_UT<<<256, 128>>>(t_start, steps, te_w1, te_b1, te_lng, te_lnb);
    k_TT<<<dim3((steps + 15) / 16, 4), 256>>>(steps);
    k_seq<<<G, NT, SMEM_BYTES>>>(w_hh,
                                 se_w1, se_b1, se_lng, se_lnb,
                                 sh_w1, sh_b1, sh_w2, sh_b2, sh_w3, sh_b3,
                                 dh_w1, dh_b1, dh_w2, dh_b2,
                                 steps, out);
}